// round 14
// baseline (speedup 1.0000x reference)
#include <cuda_runtime.h>
#include <cuda_bf16.h>
#include <cstdint>

// EdgeConv: message MLP over edges + mean-aggregate + update MLP + residual.
// R14: R13 (WIN) + node kernel converted to bf16 MMA. Edge kernel unchanged:
// direct permuted LDG.128 P/Q loads, ea MMA, RED.128 scatter. W2 folded into
// node weights. Node: [x|agg*inv] bf16 GEMM (fp32 accum), fp32 x residual.

#define ND      64
#define EDIM    16
#define HID     64
#define MAXN    100000

#define LDW_H   88    // bf16 weight row stride (176B)
#define LDX_H   72    // pq x-tile row stride (144B)
#define LDN_H   136   // node input row stride (272B), ldsm conflict-free

__device__ float         g_agg[(size_t)MAXN * HID];   // permuted h-sums
__device__ float         g_cnt[MAXN];
__device__ __nv_bfloat16 g_P[(size_t)MAXN * HID];     // permuted x@W1a + b1
__device__ __nv_bfloat16 g_Q[(size_t)MAXN * HID];     // permuted x@W1b
__device__ float         g_Wu2[2 * ND * HID];         // [Wu_top; perm(W2@Wu_bot)]
__device__ float         g_b2u[HID];

static __device__ __forceinline__ uint32_t s2u(const void* p) {
    return (uint32_t)__cvta_generic_to_shared(p);
}
static __device__ __forceinline__ void ldsm_x4(uint32_t addr, uint32_t& r0,
                                               uint32_t& r1, uint32_t& r2,
                                               uint32_t& r3) {
    asm volatile("ldmatrix.sync.aligned.m8n8.x4.shared.b16 {%0,%1,%2,%3}, [%4];"
                 : "=r"(r0), "=r"(r1), "=r"(r2), "=r"(r3) : "r"(addr));
}
static __device__ __forceinline__ void ldsm_x4t(uint32_t addr, uint32_t& r0,
                                                uint32_t& r1, uint32_t& r2,
                                                uint32_t& r3) {
    asm volatile("ldmatrix.sync.aligned.m8n8.x4.trans.shared.b16 {%0,%1,%2,%3}, [%4];"
                 : "=r"(r0), "=r"(r1), "=r"(r2), "=r"(r3) : "r"(addr));
}
static __device__ __forceinline__ void mma16816(float* c, uint32_t a0, uint32_t a1,
                                                uint32_t a2, uint32_t a3,
                                                uint32_t b0, uint32_t b1) {
    asm volatile(
        "mma.sync.aligned.m16n8k16.row.col.f32.bf16.bf16.f32 "
        "{%0,%1,%2,%3}, {%4,%5,%6,%7}, {%8,%9}, {%0,%1,%2,%3};"
        : "+f"(c[0]), "+f"(c[1]), "+f"(c[2]), "+f"(c[3])
        : "r"(a0), "r"(a1), "r"(a2), "r"(a3), "r"(b0), "r"(b1));
}
static __device__ __forceinline__ uint32_t cvt2(float lo, float hi) {
    __nv_bfloat162 p = __floats2bfloat162_rn(lo, hi);
    return *reinterpret_cast<uint32_t*>(&p);
}
static __device__ __forceinline__ float2 bf2f(uint32_t u) {
    return __bfloat1622float2(*reinterpret_cast<__nv_bfloat162*>(&u));
}

// ---------------------------------------------------------------------------
__global__ void zero_kernel(int N) {
    long long i = (long long)blockIdx.x * blockDim.x + threadIdx.x;
    long long stride = (long long)gridDim.x * blockDim.x;
    float4* a4 = reinterpret_cast<float4*>(g_agg);
    long long n4 = (long long)N * (HID / 4);
    float4 z = make_float4(0.f, 0.f, 0.f, 0.f);
    for (long long j = i; j < n4; j += stride) a4[j] = z;
    for (long long j = i; j < N; j += stride) g_cnt[j] = 0.f;
}

// ---------------------------------------------------------------------------
__global__ void w2u_kernel(const float* __restrict__ W2,
                           const float* __restrict__ Wu,
                           const float* __restrict__ b2) {
    int i = blockIdx.x * blockDim.x + threadIdx.x;
    if (i < ND * HID) {
        g_Wu2[i] = Wu[i];
    } else if (i < 2 * ND * HID) {
        int r = (i - ND * HID) >> 6, n = i & 63;
        int tt = r >> 4, jj = (r & 15) >> 1, bb = r & 1;
        int m = 8 * jj + 2 * tt + bb;
        float s = 0.f;
        for (int k = 0; k < HID; k++)
            s += W2[m * HID + k] * Wu[(ND + k) * HID + n];
        g_Wu2[i] = s;
    } else if (i < 2 * ND * HID + HID) {
        int n = i - 2 * ND * HID;
        float s = 0.f;
        for (int k = 0; k < HID; k++)
            s += b2[k] * Wu[(ND + k) * HID + n];
        g_b2u[n] = s;
    }
}

// ---------------------------------------------------------------------------
// pq_kernel: P = x@W1[0:64] + b1, Q = x@W1[64:128]; permuted bf16 outputs.
// ---------------------------------------------------------------------------
__global__ void __launch_bounds__(256)
pq_kernel(const float* __restrict__ x, const float* __restrict__ W1,
          const float* __restrict__ b1, int N, int ntiles) {
    extern __shared__ __align__(16) char smq[];
    __nv_bfloat16* sWa = reinterpret_cast<__nv_bfloat16*>(smq);
    __nv_bfloat16* sWb = sWa + 64 * LDW_H;
    __nv_bfloat16* sX  = sWb + 64 * LDW_H;

    const int tid = threadIdx.x;
    for (int i = tid; i < 64 * 64; i += 256) {
        int k = i >> 6, n = i & 63;
        sWa[k * LDW_H + n] = __float2bfloat16_rn(W1[k * HID + n]);
        sWb[k * LDW_H + n] = __float2bfloat16_rn(W1[(64 + k) * HID + n]);
    }
    __syncthreads();

    const int wid = tid >> 5, lane = tid & 31;
    const int gq = lane >> 2, tq = lane & 3;
    const int el = lane >> 1, part = lane & 1;

    float2 bias1[8];
#pragma unroll
    for (int j = 0; j < 8; j++) {
        bias1[j].x = b1[8 * j + 2 * tq];
        bias1[j].y = b1[8 * j + 2 * tq + 1];
    }

    __nv_bfloat16* myX = sX + wid * 16 * LDX_H;
    const uint32_t xBase = s2u(myX) + (((lane & 15) * LDX_H) + 8 * (lane >> 4)) * 2;
    const uint32_t waBase = s2u(sWa) + (((lane & 15) * LDW_H) + 8 * (lane >> 4)) * 2;
    const uint32_t wbBase = s2u(sWb) + (((lane & 15) * LDW_H) + 8 * (lane >> 4)) * 2;

    for (int t = blockIdx.x * 8 + wid; t < ntiles; t += gridDim.x * 8) {
        const int n0 = t * 16;
        {
            const int n = n0 + el;
            uint4* dst = reinterpret_cast<uint4*>(myX + el * LDX_H + part * 32);
            if (n < N) {
                const float4* xr = reinterpret_cast<const float4*>(
                    x + (size_t)n * ND) + part * 8;
#pragma unroll
                for (int i = 0; i < 4; i++) {
                    float4 a = xr[2 * i], b = xr[2 * i + 1];
                    uint4 u;
                    u.x = cvt2(a.x, a.y); u.y = cvt2(a.z, a.w);
                    u.z = cvt2(b.x, b.y); u.w = cvt2(b.z, b.w);
                    dst[i] = u;
                }
            } else {
                uint4 z = make_uint4(0, 0, 0, 0);
#pragma unroll
                for (int i = 0; i < 4; i++) dst[i] = z;
            }
        }
        __syncwarp();

        float accP[8][4], accQ[8][4];
#pragma unroll
        for (int j = 0; j < 8; j++)
#pragma unroll
            for (int q = 0; q < 4; q++) { accP[j][q] = 0.f; accQ[j][q] = 0.f; }

#pragma unroll
        for (int k = 0; k < 4; k++) {
            uint32_t a0, a1, a2, a3;
            ldsm_x4(xBase + k * 32, a0, a1, a2, a3);
#pragma unroll
            for (int nb = 0; nb < 4; nb++) {
                uint32_t p0, p1, p2, p3;
                ldsm_x4t(waBase + (k * 16 * LDW_H + nb * 16) * 2, p0, p1, p2, p3);
                mma16816(accP[2 * nb],     a0, a1, a2, a3, p0, p1);
                mma16816(accP[2 * nb + 1], a0, a1, a2, a3, p2, p3);
                ldsm_x4t(wbBase + (k * 16 * LDW_H + nb * 16) * 2, p0, p1, p2, p3);
                mma16816(accQ[2 * nb],     a0, a1, a2, a3, p0, p1);
                mma16816(accQ[2 * nb + 1], a0, a1, a2, a3, p2, p3);
            }
        }

        const int r0n = n0 + gq, r1n = n0 + gq + 8;
        uint4 u;
        if (r0n < N) {
            uint32_t* Pp = reinterpret_cast<uint32_t*>(g_P + (size_t)r0n * HID) + 8 * tq;
            uint32_t* Qp = reinterpret_cast<uint32_t*>(g_Q + (size_t)r0n * HID) + 8 * tq;
            u.x = cvt2(accP[0][0] + bias1[0].x, accP[0][1] + bias1[0].y);
            u.y = cvt2(accP[1][0] + bias1[1].x, accP[1][1] + bias1[1].y);
            u.z = cvt2(accP[2][0] + bias1[2].x, accP[2][1] + bias1[2].y);
            u.w = cvt2(accP[3][0] + bias1[3].x, accP[3][1] + bias1[3].y);
            reinterpret_cast<uint4*>(Pp)[0] = u;
            u.x = cvt2(accP[4][0] + bias1[4].x, accP[4][1] + bias1[4].y);
            u.y = cvt2(accP[5][0] + bias1[5].x, accP[5][1] + bias1[5].y);
            u.z = cvt2(accP[6][0] + bias1[6].x, accP[6][1] + bias1[6].y);
            u.w = cvt2(accP[7][0] + bias1[7].x, accP[7][1] + bias1[7].y);
            reinterpret_cast<uint4*>(Pp)[1] = u;
            u.x = cvt2(accQ[0][0], accQ[0][1]);
            u.y = cvt2(accQ[1][0], accQ[1][1]);
            u.z = cvt2(accQ[2][0], accQ[2][1]);
            u.w = cvt2(accQ[3][0], accQ[3][1]);
            reinterpret_cast<uint4*>(Qp)[0] = u;
            u.x = cvt2(accQ[4][0], accQ[4][1]);
            u.y = cvt2(accQ[5][0], accQ[5][1]);
            u.z = cvt2(accQ[6][0], accQ[6][1]);
            u.w = cvt2(accQ[7][0], accQ[7][1]);
            reinterpret_cast<uint4*>(Qp)[1] = u;
        }
        if (r1n < N) {
            uint32_t* Pp = reinterpret_cast<uint32_t*>(g_P + (size_t)r1n * HID) + 8 * tq;
            uint32_t* Qp = reinterpret_cast<uint32_t*>(g_Q + (size_t)r1n * HID) + 8 * tq;
            u.x = cvt2(accP[0][2] + bias1[0].x, accP[0][3] + bias1[0].y);
            u.y = cvt2(accP[1][2] + bias1[1].x, accP[1][3] + bias1[1].y);
            u.z = cvt2(accP[2][2] + bias1[2].x, accP[2][3] + bias1[2].y);
            u.w = cvt2(accP[3][2] + bias1[3].x, accP[3][3] + bias1[3].y);
            reinterpret_cast<uint4*>(Pp)[0] = u;
            u.x = cvt2(accP[4][2] + bias1[4].x, accP[4][3] + bias1[4].y);
            u.y = cvt2(accP[5][2] + bias1[5].x, accP[5][3] + bias1[5].y);
            u.z = cvt2(accP[6][2] + bias1[6].x, accP[6][3] + bias1[6].y);
            u.w = cvt2(accP[7][2] + bias1[7].x, accP[7][3] + bias1[7].y);
            reinterpret_cast<uint4*>(Pp)[1] = u;
            u.x = cvt2(accQ[0][2], accQ[0][3]);
            u.y = cvt2(accQ[1][2], accQ[1][3]);
            u.z = cvt2(accQ[2][2], accQ[2][3]);
            u.w = cvt2(accQ[3][2], accQ[3][3]);
            reinterpret_cast<uint4*>(Qp)[0] = u;
            u.x = cvt2(accQ[4][2], accQ[4][3]);
            u.y = cvt2(accQ[5][2], accQ[5][3]);
            u.z = cvt2(accQ[6][2], accQ[6][3]);
            u.w = cvt2(accQ[7][2], accQ[7][3]);
            reinterpret_cast<uint4*>(Qp)[1] = u;
        }
        __syncwarp();
    }
}

// ---------------------------------------------------------------------------
// Edge kernel: UNCHANGED from R13 (WIN).
// ---------------------------------------------------------------------------
__global__ void __launch_bounds__(512, 1)
edge_kernel(const int* __restrict__ eidx, const float* __restrict__ ea,
            const float* __restrict__ W1, int E, int nt) {
    __shared__ __align__(16) __nv_bfloat16 sW1c[16 * LDW_H];
    const int tid = threadIdx.x;
    for (int i = tid; i < 16 * HID; i += 512) {
        int k = i >> 6, n = i & 63;
        sW1c[k * LDW_H + n] = __float2bfloat16_rn(W1[(128 + k) * HID + n]);
    }
    __syncthreads();

    const int wid = tid >> 5, lane = tid & 31;
    const int gq = lane >> 2, tq = lane & 3;

    const uint32_t w1cBase = s2u(sW1c) + (((lane & 15) * LDW_H) + 8 * (lane >> 4)) * 2;
    uint32_t w1f[4][4];
#pragma unroll
    for (int nb = 0; nb < 4; nb++)
        ldsm_x4t(w1cBase + (nb * 16) * 2, w1f[nb][0], w1f[nb][1],
                 w1f[nb][2], w1f[nb][3]);

    const int gw = blockIdx.x * 16 + wid;
    const int gs = gridDim.x * 16;
    const int* __restrict__ srcp = eidx;
    const int* __restrict__ dstp = eidx + E;

    int sA = 0, sB = 0, dA = -1, dB = -1;
    if (gw < nt) {
        const int eA = gw * 16 + gq, eB = eA + 8;
        if (eA < E) { sA = srcp[eA]; dA = dstp[eA]; }
        if (eB < E) { sB = srcp[eB]; dB = dstp[eB]; }
    }

    for (int t = gw; t < nt; t += gs) {
        const uint4* PsA = reinterpret_cast<const uint4*>(g_P + (size_t)sA * HID) + 2 * tq;
        const uint4* QdA = reinterpret_cast<const uint4*>(g_Q + (size_t)((dA >= 0) ? dA : 0) * HID) + 2 * tq;
        const uint4* PsB = reinterpret_cast<const uint4*>(g_P + (size_t)sB * HID) + 2 * tq;
        const uint4* QdB = reinterpret_cast<const uint4*>(g_Q + (size_t)((dB >= 0) ? dB : 0) * HID) + 2 * tq;
        uint32_t pA[8], qA[8], pB[8], qB[8];
        *reinterpret_cast<uint4*>(&pA[0]) = PsA[0];
        *reinterpret_cast<uint4*>(&pA[4]) = PsA[1];
        *reinterpret_cast<uint4*>(&qA[0]) = QdA[0];
        *reinterpret_cast<uint4*>(&qA[4]) = QdA[1];
        *reinterpret_cast<uint4*>(&pB[0]) = PsB[0];
        *reinterpret_cast<uint4*>(&pB[4]) = PsB[1];
        *reinterpret_cast<uint4*>(&qB[0]) = QdB[0];
        *reinterpret_cast<uint4*>(&qB[4]) = QdB[1];

        const int eA = t * 16 + gq, eB = eA + 8;
        float2 e0 = make_float2(0.f, 0.f), e1 = e0, e2v = e0, e3 = e0;
        if (dA >= 0) {
            const float2* p = reinterpret_cast<const float2*>(ea + (size_t)eA * EDIM);
            e0 = p[tq]; e1 = p[tq + 4];
        }
        if (dB >= 0) {
            const float2* p = reinterpret_cast<const float2*>(ea + (size_t)eB * EDIM);
            e2v = p[tq]; e3 = p[tq + 4];
        }

        const int curdA = dA, curdB = dB;
        {
            const int tn = t + gs;
            int nsA = 0, nsB = 0, ndA = -1, ndB = -1;
            if (tn < nt) {
                const int neA = tn * 16 + gq, neB = neA + 8;
                if (neA < E) { nsA = srcp[neA]; ndA = dstp[neA]; }
                if (neB < E) { nsB = srcp[neB]; ndB = dstp[neB]; }
            }
            sA = nsA; sB = nsB; dA = ndA; dB = ndB;
        }

        const uint32_t a0 = cvt2(e0.x, e0.y);
        const uint32_t a1 = cvt2(e2v.x, e2v.y);
        const uint32_t a2 = cvt2(e1.x, e1.y);
        const uint32_t a3 = cvt2(e3.x, e3.y);

        float acc[8][4];
#pragma unroll
        for (int j = 0; j < 8; j++)
#pragma unroll
            for (int q = 0; q < 4; q++) acc[j][q] = 0.f;
#pragma unroll
        for (int nb = 0; nb < 4; nb++) {
            mma16816(acc[2 * nb],     a0, a1, a2, a3, w1f[nb][0], w1f[nb][1]);
            mma16816(acc[2 * nb + 1], a0, a1, a2, a3, w1f[nb][2], w1f[nb][3]);
        }

#pragma unroll
        for (int j = 0; j < 8; j++) {
            float2 pa = bf2f(pA[j]), qa = bf2f(qA[j]);
            float2 pb = bf2f(pB[j]), qb = bf2f(qB[j]);
            acc[j][0] = fmaxf(acc[j][0] + pa.x + qa.x, 0.f);
            acc[j][1] = fmaxf(acc[j][1] + pa.y + qa.y, 0.f);
            acc[j][2] = fmaxf(acc[j][2] + pb.x + qb.x, 0.f);
            acc[j][3] = fmaxf(acc[j][3] + pb.y + qb.y, 0.f);
        }

        if (curdA >= 0) {
            float* b = g_agg + (size_t)curdA * HID + tq * 16;
            atomicAdd(reinterpret_cast<float4*>(b + 0),
                      make_float4(acc[0][0], acc[0][1], acc[1][0], acc[1][1]));
            atomicAdd(reinterpret_cast<float4*>(b + 4),
                      make_float4(acc[2][0], acc[2][1], acc[3][0], acc[3][1]));
            atomicAdd(reinterpret_cast<float4*>(b + 8),
                      make_float4(acc[4][0], acc[4][1], acc[5][0], acc[5][1]));
            atomicAdd(reinterpret_cast<float4*>(b + 12),
                      make_float4(acc[6][0], acc[6][1], acc[7][0], acc[7][1]));
            if (tq == 0) atomicAdd(&g_cnt[curdA], 1.0f);
        }
        if (curdB >= 0) {
            float* b = g_agg + (size_t)curdB * HID + tq * 16;
            atomicAdd(reinterpret_cast<float4*>(b + 0),
                      make_float4(acc[0][2], acc[0][3], acc[1][2], acc[1][3]));
            atomicAdd(reinterpret_cast<float4*>(b + 4),
                      make_float4(acc[2][2], acc[2][3], acc[3][2], acc[3][3]));
            atomicAdd(reinterpret_cast<float4*>(b + 8),
                      make_float4(acc[4][2], acc[4][3], acc[5][2], acc[5][3]));
            atomicAdd(reinterpret_cast<float4*>(b + 12),
                      make_float4(acc[6][2], acc[6][3], acc[7][2], acc[7][3]));
            if (tq == 1) atomicAdd(&g_cnt[curdB], 1.0f);
        }
    }
}

// ---------------------------------------------------------------------------
// Node kernel (bf16 MMA): out = x + relu([x|agg*inv] @ Wu2 + bu + f*b2u).
// 256 thr = 8 warps, each warp owns 16-node tiles. Residual uses fp32 x.
// ---------------------------------------------------------------------------
__global__ void __launch_bounds__(256)
node_kernel(const float* __restrict__ x, const float* __restrict__ bu,
            float* __restrict__ out, int N, int ntiles) {
    extern __shared__ __align__(16) char smn[];
    __nv_bfloat16* sW  = reinterpret_cast<__nv_bfloat16*>(smn);   // 128*88
    float* sBu  = reinterpret_cast<float*>(sW + 2 * ND * LDW_H);  // 64
    float* sB2u = sBu + HID;                                      // 64
    float* sF   = sB2u + HID;                                     // 8*16
    __nv_bfloat16* sIn = reinterpret_cast<__nv_bfloat16*>(sF + 128); // 8*16*136

    const int tid = threadIdx.x;
    for (int i = tid; i < 2 * ND * HID; i += 256) {
        int k = i >> 6, n = i & 63;
        sW[k * LDW_H + n] = __float2bfloat16_rn(g_Wu2[i]);
    }
    if (tid < HID) { sBu[tid] = bu[tid]; sB2u[tid] = g_b2u[tid]; }
    __syncthreads();

    const int wid = tid >> 5, lane = tid & 31;
    const int gq = lane >> 2, tq = lane & 3;
    const int el = lane >> 1, part = lane & 1;

    float2 bu2[8], b2u2[8];
#pragma unroll
    for (int j = 0; j < 8; j++) {
        const int c = 8 * j + 2 * tq;
        bu2[j].x = sBu[c];     bu2[j].y = sBu[c + 1];
        b2u2[j].x = sB2u[c];   b2u2[j].y = sB2u[c + 1];
    }

    __nv_bfloat16* myIn = sIn + wid * 16 * LDN_H;
    float* myF = sF + wid * 16;
    const uint32_t inBase = s2u(myIn) + (((lane & 15) * LDN_H) + 8 * (lane >> 4)) * 2;
    const uint32_t wBase  = s2u(sW) + (((lane & 15) * LDW_H) + 8 * (lane >> 4)) * 2;

    for (int t = blockIdx.x * 8 + wid; t < ntiles; t += gridDim.x * 8) {
        const int n0 = t * 16;
        const int n = n0 + el;
        // ---- build input row: part0 -> x cols [0,64); part1 -> agg*inv ----
        {
            uint4* dst = reinterpret_cast<uint4*>(myIn + el * LDN_H + part * 64);
            if (n < N) {
                if (part == 0) {
                    const float4* xr = reinterpret_cast<const float4*>(x + (size_t)n * ND);
#pragma unroll
                    for (int i = 0; i < 8; i++) {
                        float4 a = xr[2 * i], b = xr[2 * i + 1];
                        uint4 u;
                        u.x = cvt2(a.x, a.y); u.y = cvt2(a.z, a.w);
                        u.z = cvt2(b.x, b.y); u.w = cvt2(b.z, b.w);
                        dst[i] = u;
                    }
                } else {
                    const float cnt = g_cnt[n];
                    const float inv = 1.0f / (cnt + 1e-6f);
                    myF[el] = cnt * inv;
                    const float4* ar = reinterpret_cast<const float4*>(g_agg + (size_t)n * HID);
#pragma unroll
                    for (int i = 0; i < 8; i++) {
                        float4 a = ar[2 * i], b = ar[2 * i + 1];
                        uint4 u;
                        u.x = cvt2(a.x * inv, a.y * inv); u.y = cvt2(a.z * inv, a.w * inv);
                        u.z = cvt2(b.x * inv, b.y * inv); u.w = cvt2(b.z * inv, b.w * inv);
                        dst[i] = u;
                    }
                }
            } else {
                uint4 z = make_uint4(0, 0, 0, 0);
#pragma unroll
                for (int i = 0; i < 8; i++) dst[i] = z;
                if (part == 1) myF[el] = 0.f;
            }
        }
        __syncwarp();

        // ---- GEMM: (16 x 128) @ (128 x 64) ----
        float acc[8][4];
#pragma unroll
        for (int j = 0; j < 8; j++)
#pragma unroll
            for (int q = 0; q < 4; q++) acc[j][q] = 0.f;
#pragma unroll
        for (int k = 0; k < 8; k++) {
            uint32_t a0, a1, a2, a3;
            ldsm_x4(inBase + k * 32, a0, a1, a2, a3);
#pragma unroll
            for (int nb = 0; nb < 4; nb++) {
                uint32_t p0, p1, p2, p3;
                ldsm_x4t(wBase + (k * 16 * LDW_H + nb * 16) * 2, p0, p1, p2, p3);
                mma16816(acc[2 * nb],     a0, a1, a2, a3, p0, p1);
                mma16816(acc[2 * nb + 1], a0, a1, a2, a3, p2, p3);
            }
        }
        __syncwarp();

        // ---- epilogue: r = acc + bu + f*b2u, relu; stage f32 into rows ----
        {
            const float fA = myF[gq], fB = myF[gq + 8];
            float* rowA = reinterpret_cast<float*>(myIn + gq * LDN_H);
            float* rowB = reinterpret_cast<float*>(myIn + (gq + 8) * LDN_H);
#pragma unroll
            for (int j = 0; j < 8; j++) {
                const int c = 8 * j + 2 * tq;
                float2 vA, vB;
                vA.x = fmaxf(acc[j][0] + bu2[j].x + fA * b2u2[j].x, 0.f);
                vA.y = fmaxf(acc[j][1] + bu2[j].y + fA * b2u2[j].y, 0.f);
                vB.x = fmaxf(acc[j][2] + bu2[j].x + fB * b2u2[j].x, 0.f);
                vB.y = fmaxf(acc[j][3] + bu2[j].y + fB * b2u2[j].y, 0.f);
                *reinterpret_cast<float2*>(rowA + c) = vA;
                *reinterpret_cast<float2*>(rowB + c) = vB;
            }
        }
        __syncwarp();

        // ---- output: out = x (fp32) + staged relu-result, coalesced ----
        if (n < N) {
            const float* r = reinterpret_cast<const float*>(myIn + el * LDN_H) + part * 32;
            const float4* xr = reinterpret_cast<const float4*>(x + (size_t)n * ND) + part * 8;
            float4* o = reinterpret_cast<float4*>(out + (size_t)n * ND) + part * 8;
#pragma unroll
            for (int i = 0; i < 8; i++) {
                float4 rv = *reinterpret_cast<const float4*>(r + 4 * i);
                float4 xv = xr[i];
                o[i] = make_float4(xv.x + rv.x, xv.y + rv.y, xv.z + rv.z, xv.w + rv.w);
            }
        }
        __syncwarp();
    }
}

// ---------------------------------------------------------------------------
extern "C" void kernel_launch(void* const* d_in, const int* in_sizes, int n_in,
                              void* d_out, int out_size) {
    const float* x   = (const float*)d_in[0];
    const int*   ei  = (const int*)d_in[1];
    const float* ea  = (const float*)d_in[2];
    const float* W1  = (const float*)d_in[3];
    const float* b1  = (const float*)d_in[4];
    const float* W2  = (const float*)d_in[5];
    const float* b2  = (const float*)d_in[6];
    const float* Wu  = (const float*)d_in[7];
    const float* bu  = (const float*)d_in[8];
    float* out = (float*)d_out;

    const int N = in_sizes[0] / ND;     // 100000
    const int E = in_sizes[2] / EDIM;   // 1600000

    const int smem_pq   = (2 * 64 * LDW_H + 8 * 16 * LDX_H) * 2;
    const int smem_node = 2 * ND * LDW_H * 2 + (2 * HID + 128) * 4 +
                          8 * 16 * LDN_H * 2;

    cudaFuncSetAttribute(pq_kernel, cudaFuncAttributeMaxDynamicSharedMemorySize,
                         smem_pq);
    cudaFuncSetAttribute(node_kernel, cudaFuncAttributeMaxDynamicSharedMemorySize,
                         smem_node);

    const int npq = (N + 15) / 16;
    const int nst = (E + 15) / 16;
    const int ntiles = (N + 15) / 16;

    zero_kernel<<<2048, 256>>>(N);
    w2u_kernel<<<(2 * ND * HID + HID + 255) / 256, 256>>>(W2, Wu, b2);
    pq_kernel<<<(npq + 7) / 8, 256, smem_pq>>>(x, W1, b1, N, npq);
    edge_kernel<<<148, 512>>>(ei, ea, W1, E, nst);
    node_kernel<<<(ntiles + 7) / 8, 256, smem_node>>>(x, bu, out, N, ntiles);
}

// round 15
// speedup vs baseline: 1.3191x; 1.3191x over previous
#include <cuda_runtime.h>
#include <cuda_bf16.h>
#include <cstdint>

// EdgeConv: message MLP over edges + mean-aggregate + update MLP + residual.
// R15: R13 (best verified) + per-edge counts moved to a separate int-histogram
// kernel (removes 3.2M predicated float atomics from the edge hot loop).
// Node kernel back to fp32 (R14's bf16 node cost 6x error margin).

#define ND      64
#define EDIM    16
#define HID     64
#define TILE_N  64
#define MAXN    100000

#define LDW_H   88    // bf16 weight row stride (176B)
#define LDX_H   72    // pq x-tile row stride (144B)

__device__ float         g_agg[(size_t)MAXN * HID];   // permuted h-sums
__device__ int           g_cnti[MAXN];
__device__ __nv_bfloat16 g_P[(size_t)MAXN * HID];     // permuted x@W1a + b1
__device__ __nv_bfloat16 g_Q[(size_t)MAXN * HID];     // permuted x@W1b
__device__ float         g_Wu2[2 * ND * HID];         // [Wu_top; perm(W2@Wu_bot)]
__device__ float         g_b2u[HID];

static __device__ __forceinline__ uint32_t s2u(const void* p) {
    return (uint32_t)__cvta_generic_to_shared(p);
}
static __device__ __forceinline__ void ldsm_x4(uint32_t addr, uint32_t& r0,
                                               uint32_t& r1, uint32_t& r2,
                                               uint32_t& r3) {
    asm volatile("ldmatrix.sync.aligned.m8n8.x4.shared.b16 {%0,%1,%2,%3}, [%4];"
                 : "=r"(r0), "=r"(r1), "=r"(r2), "=r"(r3) : "r"(addr));
}
static __device__ __forceinline__ void ldsm_x4t(uint32_t addr, uint32_t& r0,
                                                uint32_t& r1, uint32_t& r2,
                                                uint32_t& r3) {
    asm volatile("ldmatrix.sync.aligned.m8n8.x4.trans.shared.b16 {%0,%1,%2,%3}, [%4];"
                 : "=r"(r0), "=r"(r1), "=r"(r2), "=r"(r3) : "r"(addr));
}
static __device__ __forceinline__ void mma16816(float* c, uint32_t a0, uint32_t a1,
                                                uint32_t a2, uint32_t a3,
                                                uint32_t b0, uint32_t b1) {
    asm volatile(
        "mma.sync.aligned.m16n8k16.row.col.f32.bf16.bf16.f32 "
        "{%0,%1,%2,%3}, {%4,%5,%6,%7}, {%8,%9}, {%0,%1,%2,%3};"
        : "+f"(c[0]), "+f"(c[1]), "+f"(c[2]), "+f"(c[3])
        : "r"(a0), "r"(a1), "r"(a2), "r"(a3), "r"(b0), "r"(b1));
}
static __device__ __forceinline__ uint32_t cvt2(float lo, float hi) {
    __nv_bfloat162 p = __floats2bfloat162_rn(lo, hi);
    return *reinterpret_cast<uint32_t*>(&p);
}
static __device__ __forceinline__ float2 bf2f(uint32_t u) {
    return __bfloat1622float2(*reinterpret_cast<__nv_bfloat162*>(&u));
}

// ---------------------------------------------------------------------------
__global__ void zero_kernel(int N) {
    long long i = (long long)blockIdx.x * blockDim.x + threadIdx.x;
    long long stride = (long long)gridDim.x * blockDim.x;
    float4* a4 = reinterpret_cast<float4*>(g_agg);
    long long n4 = (long long)N * (HID / 4);
    float4 z = make_float4(0.f, 0.f, 0.f, 0.f);
    for (long long j = i; j < n4; j += stride) a4[j] = z;
    for (long long j = i; j < N; j += stride) g_cnti[j] = 0;
}

// cnt histogram: coalesced dst reads, int atomics
__global__ void cnt_kernel(const int* __restrict__ eidx, int E) {
    const int* dstp = eidx + E;
    int i = blockIdx.x * blockDim.x + threadIdx.x;
    int stride = gridDim.x * blockDim.x;
    for (int e = i; e < E; e += stride)
        atomicAdd(&g_cnti[dstp[e]], 1);
}

// ---------------------------------------------------------------------------
__global__ void w2u_kernel(const float* __restrict__ W2,
                           const float* __restrict__ Wu,
                           const float* __restrict__ b2) {
    int i = blockIdx.x * blockDim.x + threadIdx.x;
    if (i < ND * HID) {
        g_Wu2[i] = Wu[i];
    } else if (i < 2 * ND * HID) {
        int r = (i - ND * HID) >> 6, n = i & 63;
        int tt = r >> 4, jj = (r & 15) >> 1, bb = r & 1;
        int m = 8 * jj + 2 * tt + bb;
        float s = 0.f;
        for (int k = 0; k < HID; k++)
            s += W2[m * HID + k] * Wu[(ND + k) * HID + n];
        g_Wu2[i] = s;
    } else if (i < 2 * ND * HID + HID) {
        int n = i - 2 * ND * HID;
        float s = 0.f;
        for (int k = 0; k < HID; k++)
            s += b2[k] * Wu[(ND + k) * HID + n];
        g_b2u[n] = s;
    }
}

// ---------------------------------------------------------------------------
// pq_kernel: P = x@W1[0:64] + b1, Q = x@W1[64:128]; permuted bf16 outputs.
// ---------------------------------------------------------------------------
__global__ void __launch_bounds__(256)
pq_kernel(const float* __restrict__ x, const float* __restrict__ W1,
          const float* __restrict__ b1, int N, int ntiles) {
    extern __shared__ __align__(16) char smq[];
    __nv_bfloat16* sWa = reinterpret_cast<__nv_bfloat16*>(smq);
    __nv_bfloat16* sWb = sWa + 64 * LDW_H;
    __nv_bfloat16* sX  = sWb + 64 * LDW_H;

    const int tid = threadIdx.x;
    for (int i = tid; i < 64 * 64; i += 256) {
        int k = i >> 6, n = i & 63;
        sWa[k * LDW_H + n] = __float2bfloat16_rn(W1[k * HID + n]);
        sWb[k * LDW_H + n] = __float2bfloat16_rn(W1[(64 + k) * HID + n]);
    }
    __syncthreads();

    const int wid = tid >> 5, lane = tid & 31;
    const int gq = lane >> 2, tq = lane & 3;
    const int el = lane >> 1, part = lane & 1;

    float2 bias1[8];
#pragma unroll
    for (int j = 0; j < 8; j++) {
        bias1[j].x = b1[8 * j + 2 * tq];
        bias1[j].y = b1[8 * j + 2 * tq + 1];
    }

    __nv_bfloat16* myX = sX + wid * 16 * LDX_H;
    const uint32_t xBase = s2u(myX) + (((lane & 15) * LDX_H) + 8 * (lane >> 4)) * 2;
    const uint32_t waBase = s2u(sWa) + (((lane & 15) * LDW_H) + 8 * (lane >> 4)) * 2;
    const uint32_t wbBase = s2u(sWb) + (((lane & 15) * LDW_H) + 8 * (lane >> 4)) * 2;

    for (int t = blockIdx.x * 8 + wid; t < ntiles; t += gridDim.x * 8) {
        const int n0 = t * 16;
        {
            const int n = n0 + el;
            uint4* dst = reinterpret_cast<uint4*>(myX + el * LDX_H + part * 32);
            if (n < N) {
                const float4* xr = reinterpret_cast<const float4*>(
                    x + (size_t)n * ND) + part * 8;
#pragma unroll
                for (int i = 0; i < 4; i++) {
                    float4 a = xr[2 * i], b = xr[2 * i + 1];
                    uint4 u;
                    u.x = cvt2(a.x, a.y); u.y = cvt2(a.z, a.w);
                    u.z = cvt2(b.x, b.y); u.w = cvt2(b.z, b.w);
                    dst[i] = u;
                }
            } else {
                uint4 z = make_uint4(0, 0, 0, 0);
#pragma unroll
                for (int i = 0; i < 4; i++) dst[i] = z;
            }
        }
        __syncwarp();

        float accP[8][4], accQ[8][4];
#pragma unroll
        for (int j = 0; j < 8; j++)
#pragma unroll
            for (int q = 0; q < 4; q++) { accP[j][q] = 0.f; accQ[j][q] = 0.f; }

#pragma unroll
        for (int k = 0; k < 4; k++) {
            uint32_t a0, a1, a2, a3;
            ldsm_x4(xBase + k * 32, a0, a1, a2, a3);
#pragma unroll
            for (int nb = 0; nb < 4; nb++) {
                uint32_t p0, p1, p2, p3;
                ldsm_x4t(waBase + (k * 16 * LDW_H + nb * 16) * 2, p0, p1, p2, p3);
                mma16816(accP[2 * nb],     a0, a1, a2, a3, p0, p1);
                mma16816(accP[2 * nb + 1], a0, a1, a2, a3, p2, p3);
                ldsm_x4t(wbBase + (k * 16 * LDW_H + nb * 16) * 2, p0, p1, p2, p3);
                mma16816(accQ[2 * nb],     a0, a1, a2, a3, p0, p1);
                mma16816(accQ[2 * nb + 1], a0, a1, a2, a3, p2, p3);
            }
        }

        const int r0n = n0 + gq, r1n = n0 + gq + 8;
        uint4 u;
        if (r0n < N) {
            uint32_t* Pp = reinterpret_cast<uint32_t*>(g_P + (size_t)r0n * HID) + 8 * tq;
            uint32_t* Qp = reinterpret_cast<uint32_t*>(g_Q + (size_t)r0n * HID) + 8 * tq;
            u.x = cvt2(accP[0][0] + bias1[0].x, accP[0][1] + bias1[0].y);
            u.y = cvt2(accP[1][0] + bias1[1].x, accP[1][1] + bias1[1].y);
            u.z = cvt2(accP[2][0] + bias1[2].x, accP[2][1] + bias1[2].y);
            u.w = cvt2(accP[3][0] + bias1[3].x, accP[3][1] + bias1[3].y);
            reinterpret_cast<uint4*>(Pp)[0] = u;
            u.x = cvt2(accP[4][0] + bias1[4].x, accP[4][1] + bias1[4].y);
            u.y = cvt2(accP[5][0] + bias1[5].x, accP[5][1] + bias1[5].y);
            u.z = cvt2(accP[6][0] + bias1[6].x, accP[6][1] + bias1[6].y);
            u.w = cvt2(accP[7][0] + bias1[7].x, accP[7][1] + bias1[7].y);
            reinterpret_cast<uint4*>(Pp)[1] = u;
            u.x = cvt2(accQ[0][0], accQ[0][1]);
            u.y = cvt2(accQ[1][0], accQ[1][1]);
            u.z = cvt2(accQ[2][0], accQ[2][1]);
            u.w = cvt2(accQ[3][0], accQ[3][1]);
            reinterpret_cast<uint4*>(Qp)[0] = u;
            u.x = cvt2(accQ[4][0], accQ[4][1]);
            u.y = cvt2(accQ[5][0], accQ[5][1]);
            u.z = cvt2(accQ[6][0], accQ[6][1]);
            u.w = cvt2(accQ[7][0], accQ[7][1]);
            reinterpret_cast<uint4*>(Qp)[1] = u;
        }
        if (r1n < N) {
            uint32_t* Pp = reinterpret_cast<uint32_t*>(g_P + (size_t)r1n * HID) + 8 * tq;
            uint32_t* Qp = reinterpret_cast<uint32_t*>(g_Q + (size_t)r1n * HID) + 8 * tq;
            u.x = cvt2(accP[0][2] + bias1[0].x, accP[0][3] + bias1[0].y);
            u.y = cvt2(accP[1][2] + bias1[1].x, accP[1][3] + bias1[1].y);
            u.z = cvt2(accP[2][2] + bias1[2].x, accP[2][3] + bias1[2].y);
            u.w = cvt2(accP[3][2] + bias1[3].x, accP[3][3] + bias1[3].y);
            reinterpret_cast<uint4*>(Pp)[0] = u;
            u.x = cvt2(accP[4][2] + bias1[4].x, accP[4][3] + bias1[4].y);
            u.y = cvt2(accP[5][2] + bias1[5].x, accP[5][3] + bias1[5].y);
            u.z = cvt2(accP[6][2] + bias1[6].x, accP[6][3] + bias1[6].y);
            u.w = cvt2(accP[7][2] + bias1[7].x, accP[7][3] + bias1[7].y);
            reinterpret_cast<uint4*>(Pp)[1] = u;
            u.x = cvt2(accQ[0][2], accQ[0][3]);
            u.y = cvt2(accQ[1][2], accQ[1][3]);
            u.z = cvt2(accQ[2][2], accQ[2][3]);
            u.w = cvt2(accQ[3][2], accQ[3][3]);
            reinterpret_cast<uint4*>(Qp)[0] = u;
            u.x = cvt2(accQ[4][2], accQ[4][3]);
            u.y = cvt2(accQ[5][2], accQ[5][3]);
            u.z = cvt2(accQ[6][2], accQ[6][3]);
            u.w = cvt2(accQ[7][2], accQ[7][3]);
            reinterpret_cast<uint4*>(Qp)[1] = u;
        }
        __syncwarp();
    }
}

// ---------------------------------------------------------------------------
// Edge kernel: R13 structure; cnt atomics removed (handled by cnt_kernel).
// ---------------------------------------------------------------------------
__global__ void __launch_bounds__(512, 1)
edge_kernel(const int* __restrict__ eidx, const float* __restrict__ ea,
            const float* __restrict__ W1, int E, int nt) {
    __shared__ __align__(16) __nv_bfloat16 sW1c[16 * LDW_H];
    const int tid = threadIdx.x;
    for (int i = tid; i < 16 * HID; i += 512) {
        int k = i >> 6, n = i & 63;
        sW1c[k * LDW_H + n] = __float2bfloat16_rn(W1[(128 + k) * HID + n]);
    }
    __syncthreads();

    const int wid = tid >> 5, lane = tid & 31;
    const int gq = lane >> 2, tq = lane & 3;

    const uint32_t w1cBase = s2u(sW1c) + (((lane & 15) * LDW_H) + 8 * (lane >> 4)) * 2;
    uint32_t w1f[4][4];
#pragma unroll
    for (int nb = 0; nb < 4; nb++)
        ldsm_x4t(w1cBase + (nb * 16) * 2, w1f[nb][0], w1f[nb][1],
                 w1f[nb][2], w1f[nb][3]);

    const int gw = blockIdx.x * 16 + wid;
    const int gs = gridDim.x * 16;
    const int* __restrict__ srcp = eidx;
    const int* __restrict__ dstp = eidx + E;

    int sA = 0, sB = 0, dA = -1, dB = -1;
    if (gw < nt) {
        const int eA = gw * 16 + gq, eB = eA + 8;
        if (eA < E) { sA = srcp[eA]; dA = dstp[eA]; }
        if (eB < E) { sB = srcp[eB]; dB = dstp[eB]; }
    }

    for (int t = gw; t < nt; t += gs) {
        const uint4* PsA = reinterpret_cast<const uint4*>(g_P + (size_t)sA * HID) + 2 * tq;
        const uint4* QdA = reinterpret_cast<const uint4*>(g_Q + (size_t)((dA >= 0) ? dA : 0) * HID) + 2 * tq;
        const uint4* PsB = reinterpret_cast<const uint4*>(g_P + (size_t)sB * HID) + 2 * tq;
        const uint4* QdB = reinterpret_cast<const uint4*>(g_Q + (size_t)((dB >= 0) ? dB : 0) * HID) + 2 * tq;
        uint32_t pA[8], qA[8], pB[8], qB[8];
        *reinterpret_cast<uint4*>(&pA[0]) = PsA[0];
        *reinterpret_cast<uint4*>(&pA[4]) = PsA[1];
        *reinterpret_cast<uint4*>(&qA[0]) = QdA[0];
        *reinterpret_cast<uint4*>(&qA[4]) = QdA[1];
        *reinterpret_cast<uint4*>(&pB[0]) = PsB[0];
        *reinterpret_cast<uint4*>(&pB[4]) = PsB[1];
        *reinterpret_cast<uint4*>(&qB[0]) = QdB[0];
        *reinterpret_cast<uint4*>(&qB[4]) = QdB[1];

        const int eA = t * 16 + gq, eB = eA + 8;
        float2 e0 = make_float2(0.f, 0.f), e1 = e0, e2v = e0, e3 = e0;
        if (dA >= 0) {
            const float2* p = reinterpret_cast<const float2*>(ea + (size_t)eA * EDIM);
            e0 = p[tq]; e1 = p[tq + 4];
        }
        if (dB >= 0) {
            const float2* p = reinterpret_cast<const float2*>(ea + (size_t)eB * EDIM);
            e2v = p[tq]; e3 = p[tq + 4];
        }

        const int curdA = dA, curdB = dB;
        {
            const int tn = t + gs;
            int nsA = 0, nsB = 0, ndA = -1, ndB = -1;
            if (tn < nt) {
                const int neA = tn * 16 + gq, neB = neA + 8;
                if (neA < E) { nsA = srcp[neA]; ndA = dstp[neA]; }
                if (neB < E) { nsB = srcp[neB]; ndB = dstp[neB]; }
            }
            sA = nsA; sB = nsB; dA = ndA; dB = ndB;
        }

        const uint32_t a0 = cvt2(e0.x, e0.y);
        const uint32_t a1 = cvt2(e2v.x, e2v.y);
        const uint32_t a2 = cvt2(e1.x, e1.y);
        const uint32_t a3 = cvt2(e3.x, e3.y);

        float acc[8][4];
#pragma unroll
        for (int j = 0; j < 8; j++)
#pragma unroll
            for (int q = 0; q < 4; q++) acc[j][q] = 0.f;
#pragma unroll
        for (int nb = 0; nb < 4; nb++) {
            mma16816(acc[2 * nb],     a0, a1, a2, a3, w1f[nb][0], w1f[nb][1]);
            mma16816(acc[2 * nb + 1], a0, a1, a2, a3, w1f[nb][2], w1f[nb][3]);
        }

#pragma unroll
        for (int j = 0; j < 8; j++) {
            float2 pa = bf2f(pA[j]), qa = bf2f(qA[j]);
            float2 pb = bf2f(pB[j]), qb = bf2f(qB[j]);
            acc[j][0] = fmaxf(acc[j][0] + pa.x + qa.x, 0.f);
            acc[j][1] = fmaxf(acc[j][1] + pa.y + qa.y, 0.f);
            acc[j][2] = fmaxf(acc[j][2] + pb.x + qb.x, 0.f);
            acc[j][3] = fmaxf(acc[j][3] + pb.y + qb.y, 0.f);
        }

        if (curdA >= 0) {
            float* b = g_agg + (size_t)curdA * HID + tq * 16;
            atomicAdd(reinterpret_cast<float4*>(b + 0),
                      make_float4(acc[0][0], acc[0][1], acc[1][0], acc[1][1]));
            atomicAdd(reinterpret_cast<float4*>(b + 4),
                      make_float4(acc[2][0], acc[2][1], acc[3][0], acc[3][1]));
            atomicAdd(reinterpret_cast<float4*>(b + 8),
                      make_float4(acc[4][0], acc[4][1], acc[5][0], acc[5][1]));
            atomicAdd(reinterpret_cast<float4*>(b + 12),
                      make_float4(acc[6][0], acc[6][1], acc[7][0], acc[7][1]));
        }
        if (curdB >= 0) {
            float* b = g_agg + (size_t)curdB * HID + tq * 16;
            atomicAdd(reinterpret_cast<float4*>(b + 0),
                      make_float4(acc[0][2], acc[0][3], acc[1][2], acc[1][3]));
            atomicAdd(reinterpret_cast<float4*>(b + 4),
                      make_float4(acc[2][2], acc[2][3], acc[3][2], acc[3][3]));
            atomicAdd(reinterpret_cast<float4*>(b + 8),
                      make_float4(acc[4][2], acc[4][3], acc[5][2], acc[5][3]));
            atomicAdd(reinterpret_cast<float4*>(b + 12),
                      make_float4(acc[6][2], acc[6][3], acc[7][2], acc[7][3]));
        }
    }
}

// ---------------------------------------------------------------------------
// Node kernel (fp32, R13 version): out = x + relu([x,mean_h']@Wu2 + bu + f*b2u).
// ---------------------------------------------------------------------------
#define FMA16(ACC, AV, BV)                                                    \
  ACC[0][0] = fmaf(AV.x, BV.x, ACC[0][0]);                                    \
  ACC[0][1] = fmaf(AV.x, BV.y, ACC[0][1]);                                    \
  ACC[0][2] = fmaf(AV.x, BV.z, ACC[0][2]);                                    \
  ACC[0][3] = fmaf(AV.x, BV.w, ACC[0][3]);                                    \
  ACC[1][0] = fmaf(AV.y, BV.x, ACC[1][0]);                                    \
  ACC[1][1] = fmaf(AV.y, BV.y, ACC[1][1]);                                    \
  ACC[1][2] = fmaf(AV.y, BV.z, ACC[1][2]);                                    \
  ACC[1][3] = fmaf(AV.y, BV.w, ACC[1][3]);                                    \
  ACC[2][0] = fmaf(AV.z, BV.x, ACC[2][0]);                                    \
  ACC[2][1] = fmaf(AV.z, BV.y, ACC[2][1]);                                    \
  ACC[2][2] = fmaf(AV.z, BV.z, ACC[2][2]);                                    \
  ACC[2][3] = fmaf(AV.z, BV.w, ACC[2][3]);                                    \
  ACC[3][0] = fmaf(AV.w, BV.x, ACC[3][0]);                                    \
  ACC[3][1] = fmaf(AV.w, BV.y, ACC[3][1]);                                    \
  ACC[3][2] = fmaf(AV.w, BV.z, ACC[3][2]);                                    \
  ACC[3][3] = fmaf(AV.w, BV.w, ACC[3][3]);

__global__ void __launch_bounds__(256, 3)
node_kernel(const float* __restrict__ x, const float* __restrict__ bu,
            float* __restrict__ out, int N, int ntiles) {
    extern __shared__ float smn[];
    float* sWu  = smn;
    float* sIn  = sWu + 2 * ND * HID;
    float* sBu  = sIn + 2 * ND * TILE_N;
    float* sB2u = sBu + HID;
    float* sF   = sB2u + HID;

    const int tid = threadIdx.x;
    for (int i = tid; i < 2 * ND * HID; i += 256) sWu[i] = g_Wu2[i];
    if (tid < HID) { sBu[tid] = bu[tid]; sB2u[tid] = g_b2u[tid]; }
    __syncthreads();

    const int tx = tid & 15;
    const int ty = tid >> 4;
    const int q  = tid & 3;
    const int ng = tid >> 2;

    for (int tile = blockIdx.x; tile < ntiles; tile += gridDim.x) {
        const int n0 = tile * TILE_N;
        {
            const int n = n0 + ng;
            if (n < N) {
                const float cnt = (float)g_cnti[n];
                const float inv = 1.0f / (cnt + 1e-6f);
                if (q == 0) sF[ng] = cnt * inv;
                const float4* xr = reinterpret_cast<const float4*>(x + (size_t)n * ND);
                const float4* ar = reinterpret_cast<const float4*>(g_agg + (size_t)n * HID);
#pragma unroll
                for (int i = 0; i < 4; i++) {
                    const int f4 = q + 4 * i;
                    const int k  = f4 * 4;
                    float4 v = xr[f4];
                    sIn[(k + 0) * TILE_N + ng] = v.x;
                    sIn[(k + 1) * TILE_N + ng] = v.y;
                    sIn[(k + 2) * TILE_N + ng] = v.z;
                    sIn[(k + 3) * TILE_N + ng] = v.w;
                    float4 w = ar[f4];
                    sIn[(ND + k + 0) * TILE_N + ng] = w.x * inv;
                    sIn[(ND + k + 1) * TILE_N + ng] = w.y * inv;
                    sIn[(ND + k + 2) * TILE_N + ng] = w.z * inv;
                    sIn[(ND + k + 3) * TILE_N + ng] = w.w * inv;
                }
            }
        }
        __syncthreads();

        float acc[4][4];
#pragma unroll
        for (int a = 0; a < 4; a++)
#pragma unroll
            for (int b = 0; b < 4; b++) acc[a][b] = 0.f;

#pragma unroll 8
        for (int k = 0; k < 2 * ND; k++) {
            float4 av = *reinterpret_cast<const float4*>(&sIn[k * TILE_N + tx * 4]);
            float4 bv = *reinterpret_cast<const float4*>(&sWu[k * HID + ty * 4]);
            FMA16(acc, av, bv)
        }

#pragma unroll
        for (int ei = 0; ei < 4; ei++) {
            const int n = n0 + tx * 4 + ei;
            if (n < N) {
                const float f = sF[tx * 4 + ei];
                float4 o;
                float r;
                r = acc[ei][0] + sBu[ty * 4 + 0] + f * sB2u[ty * 4 + 0];
                o.x = sIn[(ty * 4 + 0) * TILE_N + tx * 4 + ei] + (r > 0.f ? r : 0.f);
                r = acc[ei][1] + sBu[ty * 4 + 1] + f * sB2u[ty * 4 + 1];
                o.y = sIn[(ty * 4 + 1) * TILE_N + tx * 4 + ei] + (r > 0.f ? r : 0.f);
                r = acc[ei][2] + sBu[ty * 4 + 2] + f * sB2u[ty * 4 + 2];
                o.z = sIn[(ty * 4 + 2) * TILE_N + tx * 4 + ei] + (r > 0.f ? r : 0.f);
                r = acc[ei][3] + sBu[ty * 4 + 3] + f * sB2u[ty * 4 + 3];
                o.w = sIn[(ty * 4 + 3) * TILE_N + tx * 4 + ei] + (r > 0.f ? r : 0.f);
                *reinterpret_cast<float4*>(out + (size_t)n * HID + ty * 4) = o;
            }
        }
        __syncthreads();
    }
}

// ---------------------------------------------------------------------------
extern "C" void kernel_launch(void* const* d_in, const int* in_sizes, int n_in,
                              void* d_out, int out_size) {
    const float* x   = (const float*)d_in[0];
    const int*   ei  = (const int*)d_in[1];
    const float* ea  = (const float*)d_in[2];
    const float* W1  = (const float*)d_in[3];
    const float* b1  = (const float*)d_in[4];
    const float* W2  = (const float*)d_in[5];
    const float* b2  = (const float*)d_in[6];
    const float* Wu  = (const float*)d_in[7];
    const float* bu  = (const float*)d_in[8];
    float* out = (float*)d_out;

    const int N = in_sizes[0] / ND;     // 100000
    const int E = in_sizes[2] / EDIM;   // 1600000

    const int smem_pq   = (2 * 64 * LDW_H + 8 * 16 * LDX_H) * 2;
    const int smem_node = (2 * ND * HID + 2 * ND * TILE_N + 3 * HID) * 4;

    cudaFuncSetAttribute(pq_kernel, cudaFuncAttributeMaxDynamicSharedMemorySize,
                         smem_pq);
    cudaFuncSetAttribute(node_kernel, cudaFuncAttributeMaxDynamicSharedMemorySize,
                         smem_node);

    const int npq = (N + 15) / 16;
    const int nst = (E + 15) / 16;
    const int ntiles = (N + TILE_N - 1) / TILE_N;

    zero_kernel<<<2048, 256>>>(N);
    w2u_kernel<<<(2 * ND * HID + HID + 255) / 256, 256>>>(W2, Wu, b2);
    cnt_kernel<<<1024, 256>>>(ei, E);
    pq_kernel<<<(npq + 7) / 8, 256, smem_pq>>>(x, W1, b1, N, npq);
    edge_kernel<<<148, 512>>>(ei, ea, W1, E, nst);
    node_kernel<<<456, 256, smem_node>>>(x, bu, out, N, ntiles);
}

// round 17
// speedup vs baseline: 1.3969x; 1.0589x over previous
#include <cuda_runtime.h>
#include <cuda_bf16.h>
#include <cstdint>

// EdgeConv: message MLP over edges + mean-aggregate + update MLP + residual.
// R17: fixes R16's zero/cnt race via SELF-CLEANING scratch: g_agg/g_cnti are
// statically zero and the node kernel (unique consumer) rewrites zeros after
// reading, so every launch starts clean with no zero pass. prep fuses only
// the independent roles (cnt histogram, w2u weight-fold, P/Q precompute).
// Edge/node compute identical to the verified R15 (254us) configuration.

#define ND      64
#define EDIM    16
#define HID     64
#define TILE_N  64
#define MAXN    100000

#define LDW_H   88    // bf16 weight row stride (176B)
#define LDX_H   72    // pq x-tile row stride (144B)

// prep role block counts
#define CB      128   // cnt role
#define WB      65    // w2u role
#define PB      782   // pq role ((6250 tiles + 7)/8)

__device__ float         g_agg[(size_t)MAXN * HID];   // permuted h-sums (self-cleaned)
__device__ int           g_cnti[MAXN];                // counts (self-cleaned)
__device__ __nv_bfloat16 g_P[(size_t)MAXN * HID];     // permuted x@W1a + b1
__device__ __nv_bfloat16 g_Q[(size_t)MAXN * HID];     // permuted x@W1b
__device__ float         g_Wu2[2 * ND * HID];         // [Wu_top; perm(W2@Wu_bot)]
__device__ float         g_b2u[HID];

static __device__ __forceinline__ uint32_t s2u(const void* p) {
    return (uint32_t)__cvta_generic_to_shared(p);
}
static __device__ __forceinline__ void ldsm_x4(uint32_t addr, uint32_t& r0,
                                               uint32_t& r1, uint32_t& r2,
                                               uint32_t& r3) {
    asm volatile("ldmatrix.sync.aligned.m8n8.x4.shared.b16 {%0,%1,%2,%3}, [%4];"
                 : "=r"(r0), "=r"(r1), "=r"(r2), "=r"(r3) : "r"(addr));
}
static __device__ __forceinline__ void ldsm_x4t(uint32_t addr, uint32_t& r0,
                                                uint32_t& r1, uint32_t& r2,
                                                uint32_t& r3) {
    asm volatile("ldmatrix.sync.aligned.m8n8.x4.trans.shared.b16 {%0,%1,%2,%3}, [%4];"
                 : "=r"(r0), "=r"(r1), "=r"(r2), "=r"(r3) : "r"(addr));
}
static __device__ __forceinline__ void mma16816(float* c, uint32_t a0, uint32_t a1,
                                                uint32_t a2, uint32_t a3,
                                                uint32_t b0, uint32_t b1) {
    asm volatile(
        "mma.sync.aligned.m16n8k16.row.col.f32.bf16.bf16.f32 "
        "{%0,%1,%2,%3}, {%4,%5,%6,%7}, {%8,%9}, {%0,%1,%2,%3};"
        : "+f"(c[0]), "+f"(c[1]), "+f"(c[2]), "+f"(c[3])
        : "r"(a0), "r"(a1), "r"(a2), "r"(a3), "r"(b0), "r"(b1));
}
static __device__ __forceinline__ uint32_t cvt2(float lo, float hi) {
    __nv_bfloat162 p = __floats2bfloat162_rn(lo, hi);
    return *reinterpret_cast<uint32_t*>(&p);
}
static __device__ __forceinline__ float2 bf2f(uint32_t u) {
    return __bfloat1622float2(*reinterpret_cast<__nv_bfloat162*>(&u));
}

// ---------------------------------------------------------------------------
// prep_kernel: grid-partitioned fusion of 3 INDEPENDENT prologue tasks.
//   blocks [0,CB)        : dst count histogram (g_cnti is zero at entry —
//                          static init on first call, node-kernel cleanup after)
//   blocks [CB,CB+WB)    : fold W2 into node weights (g_Wu2, g_b2u)
//   blocks [CB+WB, ...)  : P/Q precompute (bf16 MMA, permuted layout)
// ---------------------------------------------------------------------------
__global__ void __launch_bounds__(256)
prep_kernel(const float* __restrict__ x, const int* __restrict__ eidx,
            const float* __restrict__ W1, const float* __restrict__ b1,
            const float* __restrict__ W2, const float* __restrict__ Wu,
            const float* __restrict__ b2, int N, int E, int npq) {
    const int blk = blockIdx.x;
    const int tid = threadIdx.x;

    if (blk < CB) {
        // ---- cnt role ----
        const int* dstp = eidx + E;
        int i = blk * 256 + tid;
        int stride = CB * 256;
        for (int e = i; e < E; e += stride)
            atomicAdd(&g_cnti[dstp[e]], 1);
        return;
    }
    if (blk < CB + WB) {
        // ---- w2u role ----
        int i = (blk - CB) * 256 + tid;
        if (i < ND * HID) {
            g_Wu2[i] = Wu[i];
        } else if (i < 2 * ND * HID) {
            int r = (i - ND * HID) >> 6, n = i & 63;
            int tt = r >> 4, jj = (r & 15) >> 1, bb = r & 1;
            int m = 8 * jj + 2 * tt + bb;
            float s = 0.f;
            for (int k = 0; k < HID; k++)
                s += W2[m * HID + k] * Wu[(ND + k) * HID + n];
            g_Wu2[i] = s;
        } else if (i < 2 * ND * HID + HID) {
            int n = i - 2 * ND * HID;
            float s = 0.f;
            for (int k = 0; k < HID; k++)
                s += b2[k] * Wu[(ND + k) * HID + n];
            g_b2u[n] = s;
        }
        return;
    }

    // ---- pq role: P = x@W1[0:64] + b1, Q = x@W1[64:128]; permuted bf16 ----
    const int pblk = blk - (CB + WB);
    extern __shared__ __align__(16) char smq[];
    __nv_bfloat16* sWa = reinterpret_cast<__nv_bfloat16*>(smq);
    __nv_bfloat16* sWb = sWa + 64 * LDW_H;
    __nv_bfloat16* sX  = sWb + 64 * LDW_H;

    for (int i = tid; i < 64 * 64; i += 256) {
        int k = i >> 6, n = i & 63;
        sWa[k * LDW_H + n] = __float2bfloat16_rn(W1[k * HID + n]);
        sWb[k * LDW_H + n] = __float2bfloat16_rn(W1[(64 + k) * HID + n]);
    }
    __syncthreads();

    const int wid = tid >> 5, lane = tid & 31;
    const int gq = lane >> 2, tq = lane & 3;
    const int el = lane >> 1, part = lane & 1;

    float2 bias1[8];
#pragma unroll
    for (int j = 0; j < 8; j++) {
        bias1[j].x = b1[8 * j + 2 * tq];
        bias1[j].y = b1[8 * j + 2 * tq + 1];
    }

    __nv_bfloat16* myX = sX + wid * 16 * LDX_H;
    const uint32_t xBase = s2u(myX) + (((lane & 15) * LDX_H) + 8 * (lane >> 4)) * 2;
    const uint32_t waBase = s2u(sWa) + (((lane & 15) * LDW_H) + 8 * (lane >> 4)) * 2;
    const uint32_t wbBase = s2u(sWb) + (((lane & 15) * LDW_H) + 8 * (lane >> 4)) * 2;

    for (int t = pblk * 8 + wid; t < npq; t += PB * 8) {
        const int n0 = t * 16;
        {
            const int n = n0 + el;
            uint4* dst = reinterpret_cast<uint4*>(myX + el * LDX_H + part * 32);
            if (n < N) {
                const float4* xr = reinterpret_cast<const float4*>(
                    x + (size_t)n * ND) + part * 8;
#pragma unroll
                for (int i = 0; i < 4; i++) {
                    float4 a = xr[2 * i], b = xr[2 * i + 1];
                    uint4 u;
                    u.x = cvt2(a.x, a.y); u.y = cvt2(a.z, a.w);
                    u.z = cvt2(b.x, b.y); u.w = cvt2(b.z, b.w);
                    dst[i] = u;
                }
            } else {
                uint4 z = make_uint4(0, 0, 0, 0);
#pragma unroll
                for (int i = 0; i < 4; i++) dst[i] = z;
            }
        }
        __syncwarp();

        float accP[8][4], accQ[8][4];
#pragma unroll
        for (int j = 0; j < 8; j++)
#pragma unroll
            for (int q = 0; q < 4; q++) { accP[j][q] = 0.f; accQ[j][q] = 0.f; }

#pragma unroll
        for (int k = 0; k < 4; k++) {
            uint32_t a0, a1, a2, a3;
            ldsm_x4(xBase + k * 32, a0, a1, a2, a3);
#pragma unroll
            for (int nb = 0; nb < 4; nb++) {
                uint32_t p0, p1, p2, p3;
                ldsm_x4t(waBase + (k * 16 * LDW_H + nb * 16) * 2, p0, p1, p2, p3);
                mma16816(accP[2 * nb],     a0, a1, a2, a3, p0, p1);
                mma16816(accP[2 * nb + 1], a0, a1, a2, a3, p2, p3);
                ldsm_x4t(wbBase + (k * 16 * LDW_H + nb * 16) * 2, p0, p1, p2, p3);
                mma16816(accQ[2 * nb],     a0, a1, a2, a3, p0, p1);
                mma16816(accQ[2 * nb + 1], a0, a1, a2, a3, p2, p3);
            }
        }

        const int r0n = n0 + gq, r1n = n0 + gq + 8;
        uint4 u;
        if (r0n < N) {
            uint32_t* Pp = reinterpret_cast<uint32_t*>(g_P + (size_t)r0n * HID) + 8 * tq;
            uint32_t* Qp = reinterpret_cast<uint32_t*>(g_Q + (size_t)r0n * HID) + 8 * tq;
            u.x = cvt2(accP[0][0] + bias1[0].x, accP[0][1] + bias1[0].y);
            u.y = cvt2(accP[1][0] + bias1[1].x, accP[1][1] + bias1[1].y);
            u.z = cvt2(accP[2][0] + bias1[2].x, accP[2][1] + bias1[2].y);
            u.w = cvt2(accP[3][0] + bias1[3].x, accP[3][1] + bias1[3].y);
            reinterpret_cast<uint4*>(Pp)[0] = u;
            u.x = cvt2(accP[4][0] + bias1[4].x, accP[4][1] + bias1[4].y);
            u.y = cvt2(accP[5][0] + bias1[5].x, accP[5][1] + bias1[5].y);
            u.z = cvt2(accP[6][0] + bias1[6].x, accP[6][1] + bias1[6].y);
            u.w = cvt2(accP[7][0] + bias1[7].x, accP[7][1] + bias1[7].y);
            reinterpret_cast<uint4*>(Pp)[1] = u;
            u.x = cvt2(accQ[0][0], accQ[0][1]);
            u.y = cvt2(accQ[1][0], accQ[1][1]);
            u.z = cvt2(accQ[2][0], accQ[2][1]);
            u.w = cvt2(accQ[3][0], accQ[3][1]);
            reinterpret_cast<uint4*>(Qp)[0] = u;
            u.x = cvt2(accQ[4][0], accQ[4][1]);
            u.y = cvt2(accQ[5][0], accQ[5][1]);
            u.z = cvt2(accQ[6][0], accQ[6][1]);
            u.w = cvt2(accQ[7][0], accQ[7][1]);
            reinterpret_cast<uint4*>(Qp)[1] = u;
        }
        if (r1n < N) {
            uint32_t* Pp = reinterpret_cast<uint32_t*>(g_P + (size_t)r1n * HID) + 8 * tq;
            uint32_t* Qp = reinterpret_cast<uint32_t*>(g_Q + (size_t)r1n * HID) + 8 * tq;
            u.x = cvt2(accP[0][2] + bias1[0].x, accP[0][3] + bias1[0].y);
            u.y = cvt2(accP[1][2] + bias1[1].x, accP[1][3] + bias1[1].y);
            u.z = cvt2(accP[2][2] + bias1[2].x, accP[2][3] + bias1[2].y);
            u.w = cvt2(accP[3][2] + bias1[3].x, accP[3][3] + bias1[3].y);
            reinterpret_cast<uint4*>(Pp)[0] = u;
            u.x = cvt2(accP[4][2] + bias1[4].x, accP[4][3] + bias1[4].y);
            u.y = cvt2(accP[5][2] + bias1[5].x, accP[5][3] + bias1[5].y);
            u.z = cvt2(accP[6][2] + bias1[6].x, accP[6][3] + bias1[6].y);
            u.w = cvt2(accP[7][2] + bias1[7].x, accP[7][3] + bias1[7].y);
            reinterpret_cast<uint4*>(Pp)[1] = u;
            u.x = cvt2(accQ[0][2], accQ[0][3]);
            u.y = cvt2(accQ[1][2], accQ[1][3]);
            u.z = cvt2(accQ[2][2], accQ[2][3]);
            u.w = cvt2(accQ[3][2], accQ[3][3]);
            reinterpret_cast<uint4*>(Qp)[0] = u;
            u.x = cvt2(accQ[4][2], accQ[4][3]);
            u.y = cvt2(accQ[5][2], accQ[5][3]);
            u.z = cvt2(accQ[6][2], accQ[6][3]);
            u.w = cvt2(accQ[7][2], accQ[7][3]);
            reinterpret_cast<uint4*>(Qp)[1] = u;
        }
        __syncwarp();
    }
}

// ---------------------------------------------------------------------------
// Edge kernel: UNCHANGED (R13/R15 verified structure, cnt-free hot loop).
// ---------------------------------------------------------------------------
__global__ void __launch_bounds__(512, 1)
edge_kernel(const int* __restrict__ eidx, const float* __restrict__ ea,
            const float* __restrict__ W1, int E, int nt) {
    __shared__ __align__(16) __nv_bfloat16 sW1c[16 * LDW_H];
    const int tid = threadIdx.x;
    for (int i = tid; i < 16 * HID; i += 512) {
        int k = i >> 6, n = i & 63;
        sW1c[k * LDW_H + n] = __float2bfloat16_rn(W1[(128 + k) * HID + n]);
    }
    __syncthreads();

    const int wid = tid >> 5, lane = tid & 31;
    const int gq = lane >> 2, tq = lane & 3;

    const uint32_t w1cBase = s2u(sW1c) + (((lane & 15) * LDW_H) + 8 * (lane >> 4)) * 2;
    uint32_t w1f[4][4];
#pragma unroll
    for (int nb = 0; nb < 4; nb++)
        ldsm_x4t(w1cBase + (nb * 16) * 2, w1f[nb][0], w1f[nb][1],
                 w1f[nb][2], w1f[nb][3]);

    const int gw = blockIdx.x * 16 + wid;
    const int gs = gridDim.x * 16;
    const int* __restrict__ srcp = eidx;
    const int* __restrict__ dstp = eidx + E;

    int sA = 0, sB = 0, dA = -1, dB = -1;
    if (gw < nt) {
        const int eA = gw * 16 + gq, eB = eA + 8;
        if (eA < E) { sA = srcp[eA]; dA = dstp[eA]; }
        if (eB < E) { sB = srcp[eB]; dB = dstp[eB]; }
    }

    for (int t = gw; t < nt; t += gs) {
        const uint4* PsA = reinterpret_cast<const uint4*>(g_P + (size_t)sA * HID) + 2 * tq;
        const uint4* QdA = reinterpret_cast<const uint4*>(g_Q + (size_t)((dA >= 0) ? dA : 0) * HID) + 2 * tq;
        const uint4* PsB = reinterpret_cast<const uint4*>(g_P + (size_t)sB * HID) + 2 * tq;
        const uint4* QdB = reinterpret_cast<const uint4*>(g_Q + (size_t)((dB >= 0) ? dB : 0) * HID) + 2 * tq;
        uint32_t pA[8], qA[8], pB[8], qB[8];
        *reinterpret_cast<uint4*>(&pA[0]) = PsA[0];
        *reinterpret_cast<uint4*>(&pA[4]) = PsA[1];
        *reinterpret_cast<uint4*>(&qA[0]) = QdA[0];
        *reinterpret_cast<uint4*>(&qA[4]) = QdA[1];
        *reinterpret_cast<uint4*>(&pB[0]) = PsB[0];
        *reinterpret_cast<uint4*>(&pB[4]) = PsB[1];
        *reinterpret_cast<uint4*>(&qB[0]) = QdB[0];
        *reinterpret_cast<uint4*>(&qB[4]) = QdB[1];

        const int eA = t * 16 + gq, eB = eA + 8;
        float2 e0 = make_float2(0.f, 0.f), e1 = e0, e2v = e0, e3 = e0;
        if (dA >= 0) {
            const float2* p = reinterpret_cast<const float2*>(ea + (size_t)eA * EDIM);
            e0 = p[tq]; e1 = p[tq + 4];
        }
        if (dB >= 0) {
            const float2* p = reinterpret_cast<const float2*>(ea + (size_t)eB * EDIM);
            e2v = p[tq]; e3 = p[tq + 4];
        }

        const int curdA = dA, curdB = dB;
        {
            const int tn = t + gs;
            int nsA = 0, nsB = 0, ndA = -1, ndB = -1;
            if (tn < nt) {
                const int neA = tn * 16 + gq, neB = neA + 8;
                if (neA < E) { nsA = srcp[neA]; ndA = dstp[neA]; }
                if (neB < E) { nsB = srcp[neB]; ndB = dstp[neB]; }
            }
            sA = nsA; sB = nsB; dA = ndA; dB = ndB;
        }

        const uint32_t a0 = cvt2(e0.x, e0.y);
        const uint32_t a1 = cvt2(e2v.x, e2v.y);
        const uint32_t a2 = cvt2(e1.x, e1.y);
        const uint32_t a3 = cvt2(e3.x, e3.y);

        float acc[8][4];
#pragma unroll
        for (int j = 0; j < 8; j++)
#pragma unroll
            for (int q = 0; q < 4; q++) acc[j][q] = 0.f;
#pragma unroll
        for (int nb = 0; nb < 4; nb++) {
            mma16816(acc[2 * nb],     a0, a1, a2, a3, w1f[nb][0], w1f[nb][1]);
            mma16816(acc[2 * nb + 1], a0, a1, a2, a3, w1f[nb][2], w1f[nb][3]);
        }

#pragma unroll
        for (int j = 0; j < 8; j++) {
            float2 pa = bf2f(pA[j]), qa = bf2f(qA[j]);
            float2 pb = bf2f(pB[j]), qb = bf2f(qB[j]);
            acc[j][0] = fmaxf(acc[j][0] + pa.x + qa.x, 0.f);
            acc[j][1] = fmaxf(acc[j][1] + pa.y + qa.y, 0.f);
            acc[j][2] = fmaxf(acc[j][2] + pb.x + qb.x, 0.f);
            acc[j][3] = fmaxf(acc[j][3] + pb.y + qb.y, 0.f);
        }

        if (curdA >= 0) {
            float* b = g_agg + (size_t)curdA * HID + tq * 16;
            atomicAdd(reinterpret_cast<float4*>(b + 0),
                      make_float4(acc[0][0], acc[0][1], acc[1][0], acc[1][1]));
            atomicAdd(reinterpret_cast<float4*>(b + 4),
                      make_float4(acc[2][0], acc[2][1], acc[3][0], acc[3][1]));
            atomicAdd(reinterpret_cast<float4*>(b + 8),
                      make_float4(acc[4][0], acc[4][1], acc[5][0], acc[5][1]));
            atomicAdd(reinterpret_cast<float4*>(b + 12),
                      make_float4(acc[6][0], acc[6][1], acc[7][0], acc[7][1]));
        }
        if (curdB >= 0) {
            float* b = g_agg + (size_t)curdB * HID + tq * 16;
            atomicAdd(reinterpret_cast<float4*>(b + 0),
                      make_float4(acc[0][2], acc[0][3], acc[1][2], acc[1][3]));
            atomicAdd(reinterpret_cast<float4*>(b + 4),
                      make_float4(acc[2][2], acc[2][3], acc[3][2], acc[3][3]));
            atomicAdd(reinterpret_cast<float4*>(b + 8),
                      make_float4(acc[4][2], acc[4][3], acc[5][2], acc[5][3]));
            atomicAdd(reinterpret_cast<float4*>(b + 12),
                      make_float4(acc[6][2], acc[6][3], acc[7][2], acc[7][3]));
        }
    }
}

// ---------------------------------------------------------------------------
// Node kernel (fp32): out = x + relu([x, mean_h'] @ Wu2 + bu + f*b2u).
// SELF-CLEANING: after reading each node's agg row and count, writes zeros
// back so the next launch starts with clean scratch (determinism contract).
// ---------------------------------------------------------------------------
#define FMA16(ACC, AV, BV)                                                    \
  ACC[0][0] = fmaf(AV.x, BV.x, ACC[0][0]);                                    \
  ACC[0][1] = fmaf(AV.x, BV.y, ACC[0][1]);                                    \
  ACC[0][2] = fmaf(AV.x, BV.z, ACC[0][2]);                                    \
  ACC[0][3] = fmaf(AV.x, BV.w, ACC[0][3]);                                    \
  ACC[1][0] = fmaf(AV.y, BV.x, ACC[1][0]);                                    \
  ACC[1][1] = fmaf(AV.y, BV.y, ACC[1][1]);                                    \
  ACC[1][2] = fmaf(AV.y, BV.z, ACC[1][2]);                                    \
  ACC[1][3] = fmaf(AV.y, BV.w, ACC[1][3]);                                    \
  ACC[2][0] = fmaf(AV.z, BV.x, ACC[2][0]);                                    \
  ACC[2][1] = fmaf(AV.z, BV.y, ACC[2][1]);                                    \
  ACC[2][2] = fmaf(AV.z, BV.z, ACC[2][2]);                                    \
  ACC[2][3] = fmaf(AV.z, BV.w, ACC[2][3]);                                    \
  ACC[3][0] = fmaf(AV.w, BV.x, ACC[3][0]);                                    \
  ACC[3][1] = fmaf(AV.w, BV.y, ACC[3][1]);                                    \
  ACC[3][2] = fmaf(AV.w, BV.z, ACC[3][2]);                                    \
  ACC[3][3] = fmaf(AV.w, BV.w, ACC[3][3]);

__global__ void __launch_bounds__(256, 3)
node_kernel(const float* __restrict__ x, const float* __restrict__ bu,
            float* __restrict__ out, int N, int ntiles) {
    extern __shared__ float smn[];
    float* sWu  = smn;
    float* sIn  = sWu + 2 * ND * HID;
    float* sBu  = sIn + 2 * ND * TILE_N;
    float* sB2u = sBu + HID;
    float* sF   = sB2u + HID;

    const int tid = threadIdx.x;
    for (int i = tid; i < 2 * ND * HID; i += 256) sWu[i] = g_Wu2[i];
    if (tid < HID) { sBu[tid] = bu[tid]; sB2u[tid] = g_b2u[tid]; }
    __syncthreads();

    const int tx = tid & 15;
    const int ty = tid >> 4;
    const int q  = tid & 3;
    const int ng = tid >> 2;

    for (int tile = blockIdx.x; tile < ntiles; tile += gridDim.x) {
        const int n0 = tile * TILE_N;
        {
            const int n = n0 + ng;
            if (n < N) {
                const float cnt = (float)g_cnti[n];
                const float inv = 1.0f / (cnt + 1e-6f);
                if (q == 0) { sF[ng] = cnt * inv; g_cnti[n] = 0; }
                const float4* xr = reinterpret_cast<const float4*>(x + (size_t)n * ND);
                float4* ar = reinterpret_cast<float4*>(g_agg + (size_t)n * HID);
                const float4 z4 = make_float4(0.f, 0.f, 0.f, 0.f);
#pragma unroll
                for (int i = 0; i < 4; i++) {
                    const int f4 = q + 4 * i;
                    const int k  = f4 * 4;
                    float4 v = xr[f4];
                    sIn[(k + 0) * TILE_N + ng] = v.x;
                    sIn[(k + 1) * TILE_N + ng] = v.y;
                    sIn[(k + 2) * TILE_N + ng] = v.z;
                    sIn[(k + 3) * TILE_N + ng] = v.w;
                    float4 w = ar[f4];
                    ar[f4] = z4;   // self-clean for next launch
                    sIn[(ND + k + 0) * TILE_N + ng] = w.x * inv;
                    sIn[(ND + k + 1) * TILE_N + ng] = w.y * inv;
                    sIn[(ND + k + 2) * TILE_N + ng] = w.z * inv;
                    sIn[(ND + k + 3) * TILE_N + ng] = w.w * inv;
                }
            }
        }
        __syncthreads();

        float acc[4][4];
#pragma unroll
        for (int a = 0; a < 4; a++)
#pragma unroll
            for (int b = 0; b < 4; b++) acc[a][b] = 0.f;

#pragma unroll 8
        for (int k = 0; k < 2 * ND; k++) {
            float4 av = *reinterpret_cast<const float4*>(&sIn[k * TILE_N + tx * 4]);
            float4 bv = *reinterpret_cast<const float4*>(&sWu[k * HID + ty * 4]);
            FMA16(acc, av, bv)
        }

#pragma unroll
        for (int ei = 0; ei < 4; ei++) {
            const int n = n0 + tx * 4 + ei;
            if (n < N) {
                const float f = sF[tx * 4 + ei];
                float4 o;
                float r;
                r = acc[ei][0] + sBu[ty * 4 + 0] + f * sB2u[ty * 4 + 0];
                o.x = sIn[(ty * 4 + 0) * TILE_N + tx * 4 + ei] + (r > 0.f ? r : 0.f);
                r = acc[ei][1] + sBu[ty * 4 + 1] + f * sB2u[ty * 4 + 1];
                o.y = sIn[(ty * 4 + 1) * TILE_N + tx * 4 + ei] + (r > 0.f ? r : 0.f);
                r = acc[ei][2] + sBu[ty * 4 + 2] + f * sB2u[ty * 4 + 2];
                o.z = sIn[(ty * 4 + 2) * TILE_N + tx * 4 + ei] + (r > 0.f ? r : 0.f);
                r = acc[ei][3] + sBu[ty * 4 + 3] + f * sB2u[ty * 4 + 3];
                o.w = sIn[(ty * 4 + 3) * TILE_N + tx * 4 + ei] + (r > 0.f ? r : 0.f);
                *reinterpret_cast<float4*>(out + (size_t)n * HID + ty * 4) = o;
            }
        }
        __syncthreads();
    }
}

// ---------------------------------------------------------------------------
extern "C" void kernel_launch(void* const* d_in, const int* in_sizes, int n_in,
                              void* d_out, int out_size) {
    const float* x   = (const float*)d_in[0];
    const int*   ei  = (const int*)d_in[1];
    const float* ea  = (const float*)d_in[2];
    const float* W1  = (const float*)d_in[3];
    const float* b1  = (const float*)d_in[4];
    const float* W2  = (const float*)d_in[5];
    const float* b2  = (const float*)d_in[6];
    const float* Wu  = (const float*)d_in[7];
    const float* bu  = (const float*)d_in[8];
    float* out = (float*)d_out;

    const int N = in_sizes[0] / ND;     // 100000
    const int E = in_sizes[2] / EDIM;   // 1600000

    const int smem_prep = (2 * 64 * LDW_H + 8 * 16 * LDX_H) * 2;
    const int smem_node = (2 * ND * HID + 2 * ND * TILE_N + 3 * HID) * 4;

    cudaFuncSetAttribute(prep_kernel, cudaFuncAttributeMaxDynamicSharedMemorySize,
                         smem_prep);
    cudaFuncSetAttribute(node_kernel, cudaFuncAttributeMaxDynamicSharedMemorySize,
                         smem_node);

    const int npq = (N + 15) / 16;      // 6250 pq warp-tiles
    const int nst = (E + 15) / 16;
    const int ntiles = (N + TILE_N - 1) / TILE_N;

    prep_kernel<<<CB + WB + PB, 256, smem_prep>>>(
        x, ei, W1, b1, W2, Wu, b2, N, E, npq);
    edge_kernel<<<148, 512>>>(ei, ea, W1, E, nst);
    node_kernel<<<456, 256, smem_node>>>(x, bu, out, N, ntiles);
}